// round 2
// baseline (speedup 1.0000x reference)
#include <cuda_runtime.h>
#include <math.h>

#define Bb   32
#define Nn   512
#define FIN  74
#define Dd   140
#define DF   128
#define LL   4
#define NEGV (-9e15f)

static const size_t BND = (size_t)Bb * Nn * Dd;   // 2,293,760
static const size_t BNN = (size_t)Bb * Nn * Nn;   // 8,388,608

// scratch: x, h, hA, hp1, hp2, g, e, att, adj2
__device__ float g_scratch[5 * (size_t)Bb * Nn * Dd + (size_t)Bb * Dd
                           + 3 * (size_t)Bb * Nn * Nn + 1024];

// ---------------------------------------------------------------------------
// C[m,n] = A[m,k] * Bm[n,k]^T (+bias).  64x64 tile, 16x16 threads, 4x4 micro.
// ---------------------------------------------------------------------------
__global__ __launch_bounds__(256)
void gemm_bt_kernel(const float* __restrict__ A,
                    const float* __restrict__ Bm,
                    const float* __restrict__ bias,
                    float* __restrict__ C,
                    int M, int Nc, int K) {
    __shared__ float As[16][68];
    __shared__ float Bs[16][68];
    int bm = blockIdx.y * 64, bn = blockIdx.x * 64;
    int tx = threadIdx.x, ty = threadIdx.y, tid = ty * 16 + tx;
    float acc[4][4] = {};
    for (int k0 = 0; k0 < K; k0 += 16) {
#pragma unroll
        for (int i = 0; i < 4; i++) {
            int idx = tid + i * 256;
            int r = idx >> 4, kk = idx & 15;
            As[kk][r] = (k0 + kk < K) ? A[(size_t)(bm + r) * K + k0 + kk] : 0.f;
            Bs[kk][r] = (bn + r < Nc && k0 + kk < K)
                            ? Bm[(size_t)(bn + r) * K + k0 + kk] : 0.f;
        }
        __syncthreads();
#pragma unroll
        for (int kk = 0; kk < 16; kk++) {
            float a[4], bv[4];
#pragma unroll
            for (int i = 0; i < 4; i++) a[i] = As[kk][ty * 4 + i];
#pragma unroll
            for (int j = 0; j < 4; j++) bv[j] = Bs[kk][tx * 4 + j];
#pragma unroll
            for (int i = 0; i < 4; i++)
#pragma unroll
                for (int j = 0; j < 4; j++) acc[i][j] += a[i] * bv[j];
        }
        __syncthreads();
    }
    float bv4[4];
#pragma unroll
    for (int j = 0; j < 4; j++) {
        int n = bn + tx * 4 + j;
        bv4[j] = (bias && n < Nc) ? bias[n] : 0.f;
    }
#pragma unroll
    for (int i = 0; i < 4; i++) {
        int m = bm + ty * 4 + i;
        if (m >= M) continue;
#pragma unroll
        for (int j = 0; j < 4; j++) {
            int n = bn + tx * 4 + j;
            if (n < Nc) C[(size_t)m * Nc + n] = acc[i][j] + bv4[j];
        }
    }
}

// ---------------------------------------------------------------------------
// C[m,n] = A[m,k] * Bm[k,n]   (no transpose)
// ---------------------------------------------------------------------------
__global__ __launch_bounds__(256)
void gemm_nn_kernel(const float* __restrict__ A,
                    const float* __restrict__ Bm,
                    float* __restrict__ C,
                    int M, int Nc, int K) {
    __shared__ float As[16][68];
    __shared__ float Bs[16][68];
    int bm = blockIdx.y * 64, bn = blockIdx.x * 64;
    int tx = threadIdx.x, ty = threadIdx.y, tid = ty * 16 + tx;
    float acc[4][4] = {};
    for (int k0 = 0; k0 < K; k0 += 16) {
#pragma unroll
        for (int i = 0; i < 4; i++) {
            int idx = tid + i * 256;
            int r = idx >> 4, kk = idx & 15;
            As[kk][r] = (k0 + kk < K) ? A[(size_t)(bm + r) * K + k0 + kk] : 0.f;
            int k2 = idx >> 6, c = idx & 63;
            Bs[k2][c] = (k0 + k2 < K && bn + c < Nc)
                            ? Bm[(size_t)(k0 + k2) * Nc + bn + c] : 0.f;
        }
        __syncthreads();
#pragma unroll
        for (int kk = 0; kk < 16; kk++) {
            float a[4], bv[4];
#pragma unroll
            for (int i = 0; i < 4; i++) a[i] = As[kk][ty * 4 + i];
#pragma unroll
            for (int j = 0; j < 4; j++) bv[j] = Bs[kk][tx * 4 + j];
#pragma unroll
            for (int i = 0; i < 4; i++)
#pragma unroll
                for (int j = 0; j < 4; j++) acc[i][j] += a[i] * bv[j];
        }
        __syncthreads();
    }
#pragma unroll
    for (int i = 0; i < 4; i++) {
        int m = bm + ty * 4 + i;
        if (m >= M) continue;
#pragma unroll
        for (int j = 0; j < 4; j++) {
            int n = bn + tx * 4 + j;
            if (n < Nc) C[(size_t)m * Nc + n] = acc[i][j];
        }
    }
}

// ---------------------------------------------------------------------------
// adj2 = exp(-(c2 - mu)^2 / dev) + adj1
// ---------------------------------------------------------------------------
__global__ void adj2_kernel(const float* __restrict__ a1,
                            const float* __restrict__ c2,
                            const float* __restrict__ mu,
                            const float* __restrict__ dv,
                            float* __restrict__ adj2, size_t total) {
    size_t i = (size_t)blockIdx.x * blockDim.x + threadIdx.x;
    if (i >= total) return;
    float d = c2[i] - mu[0];
    adj2[i] = expf(-d * d / dv[0]) + a1[i];
}

// ---------------------------------------------------------------------------
// E[b,j,k] = dot(hA[b,j], h[b,k]) + dot(h[b,j], hA[b,k])   (e + e^T fused)
// ---------------------------------------------------------------------------
__global__ __launch_bounds__(256)
void esym_kernel(const float* __restrict__ h,
                 const float* __restrict__ hA,
                 float* __restrict__ E) {
    int b = blockIdx.z;
    const float* Hb = h + (size_t)b * Nn * Dd;
    const float* Pb = hA + (size_t)b * Nn * Dd;
    float* Eb = E + (size_t)b * Nn * Nn;
    __shared__ float Pj[16][68], Hj[16][68], Pk[16][68], Hk[16][68];
    int bj = blockIdx.y * 64, bk = blockIdx.x * 64;
    int tx = threadIdx.x, ty = threadIdx.y, tid = ty * 16 + tx;
    float acc[4][4] = {};
    for (int l0 = 0; l0 < Dd; l0 += 16) {
#pragma unroll
        for (int i = 0; i < 4; i++) {
            int idx = tid + i * 256;
            int r = idx >> 4, l = idx & 15;
            bool ok = (l0 + l) < Dd;
            Pj[l][r] = ok ? Pb[(size_t)(bj + r) * Dd + l0 + l] : 0.f;
            Hj[l][r] = ok ? Hb[(size_t)(bj + r) * Dd + l0 + l] : 0.f;
            Pk[l][r] = ok ? Pb[(size_t)(bk + r) * Dd + l0 + l] : 0.f;
            Hk[l][r] = ok ? Hb[(size_t)(bk + r) * Dd + l0 + l] : 0.f;
        }
        __syncthreads();
#pragma unroll
        for (int l = 0; l < 16; l++) {
            float pj[4], hj[4], pk[4], hk[4];
#pragma unroll
            for (int i = 0; i < 4; i++) { pj[i] = Pj[l][ty * 4 + i]; hj[i] = Hj[l][ty * 4 + i]; }
#pragma unroll
            for (int j = 0; j < 4; j++) { pk[j] = Pk[l][tx * 4 + j]; hk[j] = Hk[l][tx * 4 + j]; }
#pragma unroll
            for (int i = 0; i < 4; i++)
#pragma unroll
                for (int j = 0; j < 4; j++)
                    acc[i][j] += pj[i] * hk[j] + hj[i] * pk[j];
        }
        __syncthreads();
    }
#pragma unroll
    for (int i = 0; i < 4; i++) {
        int jr = bj + ty * 4 + i;
#pragma unroll
        for (int j = 0; j < 4; j++)
            Eb[(size_t)jr * Nn + bk + tx * 4 + j] = acc[i][j];
    }
}

// ---------------------------------------------------------------------------
// att[b,:,k] = softmax_over_rows(where(adj>0, e, NEG)) * adj
// One block handles 16 columns (full 512 rows staged in SMEM).
// ---------------------------------------------------------------------------
__global__ __launch_bounds__(256)
void softmax_kernel(const float* __restrict__ adj,
                    const float* __restrict__ e,
                    float* __restrict__ att) {
    __shared__ float sv[Nn][17];
    __shared__ float red[16][16];
    int b = blockIdx.y;
    int k = blockIdx.x * 16 + threadIdx.x;
    int tx = threadIdx.x, ty = threadIdx.y;
    const size_t base = (size_t)b * Nn * Nn;

    float m = -3.4e38f;
    for (int j = ty; j < Nn; j += 16) {
        float a = adj[base + (size_t)j * Nn + k];
        float v = (a > 0.f) ? e[base + (size_t)j * Nn + k] : NEGV;
        sv[j][tx] = v;
        m = fmaxf(m, v);
    }
    red[ty][tx] = m;
    __syncthreads();
    if (ty == 0) {
        float mm = red[0][tx];
#pragma unroll
        for (int t = 1; t < 16; t++) mm = fmaxf(mm, red[t][tx]);
        red[0][tx] = mm;
    }
    __syncthreads();
    m = red[0][tx];
    __syncthreads();

    float s = 0.f;
    for (int j = ty; j < Nn; j += 16) {
        float ev = expf(sv[j][tx] - m);
        sv[j][tx] = ev;
        s += ev;
    }
    red[ty][tx] = s;
    __syncthreads();
    if (ty == 0) {
        float ss = 0.f;
#pragma unroll
        for (int t = 0; t < 16; t++) ss += red[t][tx];
        red[0][tx] = ss;
    }
    __syncthreads();
    float inv = 1.f / red[0][tx];

    for (int j = ty; j < Nn; j += 16) {
        att[base + (size_t)j * Nn + k] =
            sv[j][tx] * inv * adj[base + (size_t)j * Nn + k];
    }
}

// ---------------------------------------------------------------------------
// hp[b,i,d] = relu( sum_j att[b,i,j] * h[b,j,d] )
// ---------------------------------------------------------------------------
__global__ __launch_bounds__(256)
void atth_kernel(const float* __restrict__ att,
                 const float* __restrict__ h,
                 float* __restrict__ hp) {
    int b = blockIdx.z;
    const float* Ab = att + (size_t)b * Nn * Nn;
    const float* Hb = h + (size_t)b * Nn * Dd;
    float* Ob = hp + (size_t)b * Nn * Dd;
    __shared__ float As[16][68], Bs[16][68];
    int bi = blockIdx.y * 64, bd = blockIdx.x * 64;
    int tx = threadIdx.x, ty = threadIdx.y, tid = ty * 16 + tx;
    float acc[4][4] = {};
    for (int j0 = 0; j0 < Nn; j0 += 16) {
#pragma unroll
        for (int i = 0; i < 4; i++) {
            int idx = tid + i * 256;
            int r = idx >> 4, jj = idx & 15;
            As[jj][r] = Ab[(size_t)(bi + r) * Nn + j0 + jj];
            int j2 = idx >> 6, c = idx & 63;
            Bs[j2][c] = (bd + c < Dd) ? Hb[(size_t)(j0 + j2) * Dd + bd + c] : 0.f;
        }
        __syncthreads();
#pragma unroll
        for (int jj = 0; jj < 16; jj++) {
            float a[4], bv[4];
#pragma unroll
            for (int i = 0; i < 4; i++) a[i] = As[jj][ty * 4 + i];
#pragma unroll
            for (int j = 0; j < 4; j++) bv[j] = Bs[jj][tx * 4 + j];
#pragma unroll
            for (int i = 0; i < 4; i++)
#pragma unroll
                for (int j = 0; j < 4; j++) acc[i][j] += a[i] * bv[j];
        }
        __syncthreads();
    }
#pragma unroll
    for (int i = 0; i < 4; i++) {
        int r = bi + ty * 4 + i;
#pragma unroll
        for (int j = 0; j < 4; j++) {
            int d = bd + tx * 4 + j;
            if (d < Dd) Ob[(size_t)r * Dd + d] = fmaxf(acc[i][j], 0.f);
        }
    }
}

// ---------------------------------------------------------------------------
// Gated combine for both branches, x_new = o2 - o1.  One warp per node.
// ---------------------------------------------------------------------------
__global__ __launch_bounds__(256)
void gate_kernel(float* __restrict__ x,
                 const float* __restrict__ hp1,
                 const float* __restrict__ hp2,
                 const float* __restrict__ gwk,
                 const float* __restrict__ gbk) {
    int warp = (blockIdx.x * blockDim.x + threadIdx.x) >> 5;
    int lane = threadIdx.x & 31;
    if (warp >= Bb * Nn) return;
    float* xr = x + (size_t)warp * Dd;
    const float* h1 = hp1 + (size_t)warp * Dd;
    const float* h2 = hp2 + (size_t)warp * Dd;
    float sx = 0.f, s1 = 0.f, s2 = 0.f;
    for (int d = lane; d < Dd; d += 32) {
        float xv = xr[d];
        sx += xv * gwk[d];
        s1 += h1[d] * gwk[Dd + d];
        s2 += h2[d] * gwk[Dd + d];
    }
#pragma unroll
    for (int o = 16; o > 0; o >>= 1) {
        sx += __shfl_xor_sync(0xffffffffu, sx, o);
        s1 += __shfl_xor_sync(0xffffffffu, s1, o);
        s2 += __shfl_xor_sync(0xffffffffu, s2, o);
    }
    float gbv = gbk[0];
    float c1 = 1.f / (1.f + expf(-(sx + s1 + gbv)));
    float c2 = 1.f / (1.f + expf(-(sx + s2 + gbv)));
    for (int d = lane; d < Dd; d += 32) {
        float xv = xr[d], a = h1[d], bv = h2[d];
        xr[d] = (c2 * xv + (1.f - c2) * bv) - (c1 * xv + (1.f - c1) * a);
    }
}

// ---------------------------------------------------------------------------
// g[b,d] = sum_n x[b,n,d] * valid[b,n]
// ---------------------------------------------------------------------------
__global__ void readout_kernel(const float* __restrict__ x,
                               const float* __restrict__ valid,
                               float* __restrict__ g) {
    int b = blockIdx.x, d = threadIdx.x;
    if (d >= Dd) return;
    const float* xb = x + (size_t)b * Nn * Dd;
    const float* vb = valid + (size_t)b * Nn;
    float s = 0.f;
    for (int n = 0; n < Nn; n++) s += xb[(size_t)n * Dd + d] * vb[n];
    g[(size_t)b * Dd + d] = s;
}

// ---------------------------------------------------------------------------
// Final MLP head: 3x (linear+relu), then linear + sigmoid. One block per b.
// ---------------------------------------------------------------------------
__global__ __launch_bounds__(128)
void mlp_kernel(const float* __restrict__ g,
                const float* __restrict__ w0, const float* __restrict__ b0,
                const float* __restrict__ w1, const float* __restrict__ b1,
                const float* __restrict__ w2, const float* __restrict__ b2,
                const float* __restrict__ w3, const float* __restrict__ b3,
                float* __restrict__ out) {
    int b = blockIdx.x, t = threadIdx.x;  // 128 threads
    __shared__ float gbuf[Dd];
    __shared__ float ha[DF];
    __shared__ float hb[DF];
    __shared__ float red[DF];
    for (int i = t; i < Dd; i += DF) gbuf[i] = g[(size_t)b * Dd + i];
    __syncthreads();
    float acc = b0[t];
    for (int k = 0; k < Dd; k++) acc += gbuf[k] * w0[(size_t)k * DF + t];
    ha[t] = fmaxf(acc, 0.f);
    __syncthreads();
    acc = b1[t];
    for (int k = 0; k < DF; k++) acc += ha[k] * w1[(size_t)k * DF + t];
    hb[t] = fmaxf(acc, 0.f);
    __syncthreads();
    acc = b2[t];
    for (int k = 0; k < DF; k++) acc += hb[k] * w2[(size_t)k * DF + t];
    ha[t] = fmaxf(acc, 0.f);
    __syncthreads();
    red[t] = ha[t] * w3[t];
    __syncthreads();
    for (int s = 64; s > 0; s >>= 1) {
        if (t < s) red[t] += red[t + s];
        __syncthreads();
    }
    if (t == 0) out[b] = 1.f / (1.f + expf(-(red[0] + b3[0])));
}

// ---------------------------------------------------------------------------
extern "C" void kernel_launch(void* const* d_in, const int* in_sizes, int n_in,
                              void* d_out, int out_size) {
    const float* c_hs  = (const float*)d_in[0];
    const float* adj1  = (const float*)d_in[1];
    const float* c2    = (const float*)d_in[2];
    const float* valid = (const float*)d_in[3];
    const float* We    = (const float*)d_in[4];
    const float* Ww    = (const float*)d_in[5];
    const float* Wb    = (const float*)d_in[6];
    const float* Amat  = (const float*)d_in[7];
    const float* gw    = (const float*)d_in[8];
    const float* gb    = (const float*)d_in[9];
    const float* mu    = (const float*)d_in[10];
    const float* dv    = (const float*)d_in[11];
    const float* w0 = (const float*)d_in[12]; const float* b0 = (const float*)d_in[13];
    const float* w1 = (const float*)d_in[14]; const float* b1 = (const float*)d_in[15];
    const float* w2 = (const float*)d_in[16]; const float* b2 = (const float*)d_in[17];
    const float* w3 = (const float*)d_in[18]; const float* b3 = (const float*)d_in[19];
    float* out = (float*)d_out;

    float* base = nullptr;
    cudaGetSymbolAddress((void**)&base, g_scratch);
    float* x    = base;
    float* h    = base + BND;
    float* hA   = base + 2 * BND;
    float* hp1  = base + 3 * BND;
    float* hp2  = base + 4 * BND;
    float* g    = base + 5 * BND;
    float* e    = g + (size_t)Bb * Dd;
    float* att  = e + BNN;
    float* adj2 = att + BNN;

    dim3 tb(16, 16);
    int M = Bb * Nn;

    // x = c_hs @ We^T
    gemm_bt_kernel<<<dim3((Dd + 63) / 64, M / 64), tb>>>(c_hs, We, nullptr, x, M, Dd, FIN);
    // adj2 = exp(-(c2-mu)^2/dev) + adj1
    adj2_kernel<<<(unsigned)((BNN + 255) / 256), 256>>>(adj1, c2, mu, dv, adj2, BNN);

    for (int k = 0; k < LL; k++) {
        const float* Wwk = Ww + (size_t)k * Dd * Dd;
        const float* Wbk = Wb + (size_t)k * Dd;
        const float* Ak  = Amat + (size_t)k * Dd * Dd;
        const float* gwk = gw + (size_t)k * 2 * Dd;
        const float* gbk = gb + k;

        gemm_bt_kernel<<<dim3(3, M / 64), tb>>>(x, Wwk, Wbk, h, M, Dd, Dd);
        gemm_nn_kernel<<<dim3(3, M / 64), tb>>>(h, Ak, hA, M, Dd, Dd);
        esym_kernel<<<dim3(Nn / 64, Nn / 64, Bb), tb>>>(h, hA, e);

        softmax_kernel<<<dim3(Nn / 16, Bb), tb>>>(adj1, e, att);
        atth_kernel<<<dim3(3, Nn / 64, Bb), tb>>>(att, h, hp1);

        softmax_kernel<<<dim3(Nn / 16, Bb), tb>>>(adj2, e, att);
        atth_kernel<<<dim3(3, Nn / 64, Bb), tb>>>(att, h, hp2);

        gate_kernel<<<(Bb * Nn) / 8, 256>>>(x, hp1, hp2, gwk, gbk);
    }

    readout_kernel<<<Bb, 160>>>(x, valid, g);
    mlp_kernel<<<Bb, DF>>>(g, w0, b0, w1, b1, w2, b2, w3, b3, out);
}

// round 3
// speedup vs baseline: 1.0715x; 1.0715x over previous
#include <cuda_runtime.h>
#include <math.h>

#define Bb   32
#define Nn   512
#define FIN  74
#define Dd   140
#define DF   128
#define LL   4
#define NEGV (-9e15f)

static const size_t BND = (size_t)Bb * Nn * Dd;
static const size_t BNN = (size_t)Bb * Nn * Nn;

// scratch: x, h, hA, hp1, hp2, g, e, att, adj2
__device__ float g_scratch[5 * (size_t)Bb * Nn * Dd + (size_t)Bb * Dd
                           + 3 * (size_t)Bb * Nn * Nn + 1024];

// ---------------------------------------------------------------------------
// TF32 helpers (3xTF32 scheme: a = hi + lo, each representable in tf32)
// ---------------------------------------------------------------------------
__device__ __forceinline__ unsigned f2tf32(float x) {
    unsigned r;
    asm("cvt.rna.tf32.f32 %0, %1;" : "=r"(r) : "f"(x));
    return r;
}

__device__ __forceinline__ void mma_tf32(float c[4], const unsigned a[4],
                                         const unsigned b[2]) {
    asm volatile(
        "mma.sync.aligned.m16n8k8.row.col.f32.tf32.tf32.f32 "
        "{%0,%1,%2,%3}, {%4,%5,%6,%7}, {%8,%9}, {%0,%1,%2,%3};\n"
        : "+f"(c[0]), "+f"(c[1]), "+f"(c[2]), "+f"(c[3])
        : "r"(a[0]), "r"(a[1]), "r"(a[2]), "r"(a[3]), "r"(b[0]), "r"(b[1]));
}

#define LDT 68  // smem leading dim (floats) for 16x64 tiles

// Warp-level 32x32 tile compute over one BK=16 smem tile pair.
// As/Bs: [16][LDT], k-major. acc[2(mf)][4(nf)][4].
__device__ __forceinline__ void warp_mma_k16(const float* __restrict__ As,
                                             const float* __restrict__ Bs,
                                             int warp_m, int warp_n, int lane,
                                             float acc[2][4][4]) {
    int quad = lane >> 2, tq = lane & 3;
#pragma unroll
    for (int k8 = 0; k8 < 16; k8 += 8) {
        unsigned Ahi[2][4], Alo[2][4];
#pragma unroll
        for (int mf = 0; mf < 2; mf++) {
            int m0 = warp_m + mf * 16;
            float a0 = As[(k8 + tq) * LDT + m0 + quad];
            float a1 = As[(k8 + tq) * LDT + m0 + quad + 8];
            float a2 = As[(k8 + tq + 4) * LDT + m0 + quad];
            float a3 = As[(k8 + tq + 4) * LDT + m0 + quad + 8];
            Ahi[mf][0] = f2tf32(a0); Alo[mf][0] = f2tf32(a0 - __uint_as_float(Ahi[mf][0]));
            Ahi[mf][1] = f2tf32(a1); Alo[mf][1] = f2tf32(a1 - __uint_as_float(Ahi[mf][1]));
            Ahi[mf][2] = f2tf32(a2); Alo[mf][2] = f2tf32(a2 - __uint_as_float(Ahi[mf][2]));
            Ahi[mf][3] = f2tf32(a3); Alo[mf][3] = f2tf32(a3 - __uint_as_float(Ahi[mf][3]));
        }
#pragma unroll
        for (int nf = 0; nf < 4; nf++) {
            int n0 = warp_n + nf * 8 + quad;
            float b0 = Bs[(k8 + tq) * LDT + n0];
            float b1 = Bs[(k8 + tq + 4) * LDT + n0];
            unsigned Bhi[2], Blo[2];
            Bhi[0] = f2tf32(b0); Blo[0] = f2tf32(b0 - __uint_as_float(Bhi[0]));
            Bhi[1] = f2tf32(b1); Blo[1] = f2tf32(b1 - __uint_as_float(Bhi[1]));
#pragma unroll
            for (int mf = 0; mf < 2; mf++) {
                mma_tf32(acc[mf][nf], Ahi[mf], Bhi);
                mma_tf32(acc[mf][nf], Ahi[mf], Blo);
                mma_tf32(acc[mf][nf], Alo[mf], Bhi);
            }
        }
    }
}

// ---------------------------------------------------------------------------
// lin_bt_tc: C[M,Nc] = A[M,K] * B[Nc,K]^T (+bias).  64x64 tile, 128 threads.
// ---------------------------------------------------------------------------
__global__ __launch_bounds__(128)
void lin_bt_tc(const float* __restrict__ A, const float* __restrict__ Bm,
               const float* __restrict__ bias, float* __restrict__ C,
               int M, int Nc, int K) {
    __shared__ float As[16][LDT], Bs[16][LDT];
    int bm = blockIdx.y * 64, bn = blockIdx.x * 64;
    int tid = threadIdx.x, lane = tid & 31, wid = tid >> 5;
    int warp_m = (wid >> 1) * 32, warp_n = (wid & 1) * 32;
    float acc[2][4][4] = {};
    int kiter = (K + 15) / 16;
    for (int kt = 0; kt < kiter; kt++) {
        int k0 = kt * 16;
#pragma unroll
        for (int i = 0; i < 8; i++) {
            int idx = tid + i * 128;
            int kk = idx & 15, r = idx >> 4;
            As[kk][r] = (k0 + kk < K) ? A[(size_t)(bm + r) * K + k0 + kk] : 0.f;
            Bs[kk][r] = (bn + r < Nc && k0 + kk < K)
                            ? Bm[(size_t)(bn + r) * K + k0 + kk] : 0.f;
        }
        __syncthreads();
        warp_mma_k16(&As[0][0], &Bs[0][0], warp_m, warp_n, lane, acc);
        __syncthreads();
    }
    int quad = lane >> 2, tq = lane & 3;
#pragma unroll
    for (int mf = 0; mf < 2; mf++)
#pragma unroll
        for (int nf = 0; nf < 4; nf++) {
            int r0 = bm + warp_m + mf * 16 + quad;
            int c0 = bn + warp_n + nf * 8 + 2 * tq;
#pragma unroll
            for (int v = 0; v < 4; v++) {
                int r = r0 + (v >> 1) * 8, c = c0 + (v & 1);
                if (c < Nc) {
                    float val = acc[mf][nf][v];
                    if (bias) val += bias[c];
                    C[(size_t)r * Nc + c] = val;
                }
            }
        }
}

// ---------------------------------------------------------------------------
// nn_tc: C[M,Nc] = A[M,K] * Bg[K,Nc]   (B k-major rows)
// ---------------------------------------------------------------------------
__global__ __launch_bounds__(128)
void nn_tc(const float* __restrict__ A, const float* __restrict__ Bg,
           float* __restrict__ C, int M, int Nc, int K) {
    __shared__ float As[16][LDT], Bs[16][LDT];
    int bm = blockIdx.y * 64, bn = blockIdx.x * 64;
    int tid = threadIdx.x, lane = tid & 31, wid = tid >> 5;
    int warp_m = (wid >> 1) * 32, warp_n = (wid & 1) * 32;
    float acc[2][4][4] = {};
    int kiter = (K + 15) / 16;
    for (int kt = 0; kt < kiter; kt++) {
        int k0 = kt * 16;
#pragma unroll
        for (int i = 0; i < 8; i++) {
            int idx = tid + i * 128;
            int kk = idx & 15, r = idx >> 4;
            As[kk][r] = (k0 + kk < K) ? A[(size_t)(bm + r) * K + k0 + kk] : 0.f;
            int k2 = idx >> 6, c = idx & 63;
            Bs[k2][c] = (k0 + k2 < K && bn + c < Nc)
                            ? Bg[(size_t)(k0 + k2) * Nc + bn + c] : 0.f;
        }
        __syncthreads();
        warp_mma_k16(&As[0][0], &Bs[0][0], warp_m, warp_n, lane, acc);
        __syncthreads();
    }
    int quad = lane >> 2, tq = lane & 3;
#pragma unroll
    for (int mf = 0; mf < 2; mf++)
#pragma unroll
        for (int nf = 0; nf < 4; nf++) {
            int r0 = bm + warp_m + mf * 16 + quad;
            int c0 = bn + warp_n + nf * 8 + 2 * tq;
#pragma unroll
            for (int v = 0; v < 4; v++) {
                int r = r0 + (v >> 1) * 8, c = c0 + (v & 1);
                if (c < Nc) C[(size_t)r * Nc + c] = acc[mf][nf][v];
            }
        }
}

// ---------------------------------------------------------------------------
// esym_tc: E[b,j,k] = sum_l hA[b,j,l]h[b,k,l] + h[b,j,l]hA[b,k,l]
// as one GEMM with Acat=[hA|h], Bcat=[h|hA], K=280 padded to 288.
// ---------------------------------------------------------------------------
__global__ __launch_bounds__(128)
void esym_tc(const float* __restrict__ h, const float* __restrict__ hA,
             float* __restrict__ E) {
    int b = blockIdx.z;
    const float* Hb = h + (size_t)b * Nn * Dd;
    const float* Pb = hA + (size_t)b * Nn * Dd;
    float* Eb = E + (size_t)b * Nn * Nn;
    __shared__ float As[16][LDT], Bs[16][LDT];
    int bm = blockIdx.y * 64, bn = blockIdx.x * 64;
    int tid = threadIdx.x, lane = tid & 31, wid = tid >> 5;
    int warp_m = (wid >> 1) * 32, warp_n = (wid & 1) * 32;
    float acc[2][4][4] = {};
    for (int kt = 0; kt < 18; kt++) {
        int k0 = kt * 16;
#pragma unroll
        for (int i = 0; i < 8; i++) {
            int idx = tid + i * 128;
            int kk = idx & 15, r = idx >> 4;
            int kg = k0 + kk;
            float av = 0.f, bv = 0.f;
            if (kg < Dd) {
                av = Pb[(size_t)(bm + r) * Dd + kg];
                bv = Hb[(size_t)(bn + r) * Dd + kg];
            } else if (kg < 2 * Dd) {
                av = Hb[(size_t)(bm + r) * Dd + kg - Dd];
                bv = Pb[(size_t)(bn + r) * Dd + kg - Dd];
            }
            As[kk][r] = av;
            Bs[kk][r] = bv;
        }
        __syncthreads();
        warp_mma_k16(&As[0][0], &Bs[0][0], warp_m, warp_n, lane, acc);
        __syncthreads();
    }
    int quad = lane >> 2, tq = lane & 3;
#pragma unroll
    for (int mf = 0; mf < 2; mf++)
#pragma unroll
        for (int nf = 0; nf < 4; nf++) {
            int r0 = bm + warp_m + mf * 16 + quad;
            int c0 = bn + warp_n + nf * 8 + 2 * tq;
#pragma unroll
            for (int v = 0; v < 4; v++)
                Eb[(size_t)(r0 + (v >> 1) * 8) * Nn + c0 + (v & 1)] = acc[mf][nf][v];
        }
}

// ---------------------------------------------------------------------------
// atth_tc: hp[b,i,d] = relu( sum_j att[b,i,j] h[b,j,d] ), K=512.
// ---------------------------------------------------------------------------
__global__ __launch_bounds__(128)
void atth_tc(const float* __restrict__ att, const float* __restrict__ h,
             float* __restrict__ hp) {
    int b = blockIdx.z;
    const float* Ab = att + (size_t)b * Nn * Nn;
    const float* Hb = h + (size_t)b * Nn * Dd;
    float* Ob = hp + (size_t)b * Nn * Dd;
    __shared__ float As[16][LDT], Bs[16][LDT];
    int bi = blockIdx.y * 64, bd = blockIdx.x * 64;
    int tid = threadIdx.x, lane = tid & 31, wid = tid >> 5;
    int warp_m = (wid >> 1) * 32, warp_n = (wid & 1) * 32;
    float acc[2][4][4] = {};
    for (int kt = 0; kt < Nn / 16; kt++) {
        int k0 = kt * 16;
#pragma unroll
        for (int i = 0; i < 8; i++) {
            int idx = tid + i * 128;
            int kk = idx & 15, r = idx >> 4;
            As[kk][r] = Ab[(size_t)(bi + r) * Nn + k0 + kk];
            int k2 = idx >> 6, c = idx & 63;
            Bs[k2][c] = (bd + c < Dd) ? Hb[(size_t)(k0 + k2) * Dd + bd + c] : 0.f;
        }
        __syncthreads();
        warp_mma_k16(&As[0][0], &Bs[0][0], warp_m, warp_n, lane, acc);
        __syncthreads();
    }
    int quad = lane >> 2, tq = lane & 3;
#pragma unroll
    for (int mf = 0; mf < 2; mf++)
#pragma unroll
        for (int nf = 0; nf < 4; nf++) {
            int r0 = bi + warp_m + mf * 16 + quad;
            int c0 = bd + warp_n + nf * 8 + 2 * tq;
#pragma unroll
            for (int v = 0; v < 4; v++) {
                int c = c0 + (v & 1);
                if (c < Dd)
                    Ob[(size_t)(r0 + (v >> 1) * 8) * Dd + c] =
                        fmaxf(acc[mf][nf][v], 0.f);
            }
        }
}

// ---------------------------------------------------------------------------
// adj2 = exp(-(c2 - mu)^2 / dev) + adj1
// ---------------------------------------------------------------------------
__global__ void adj2_kernel(const float* __restrict__ a1,
                            const float* __restrict__ c2,
                            const float* __restrict__ mu,
                            const float* __restrict__ dv,
                            float* __restrict__ adj2, size_t total) {
    size_t i = (size_t)blockIdx.x * blockDim.x + threadIdx.x;
    if (i >= total) return;
    float d = c2[i] - mu[0];
    adj2[i] = expf(-d * d / dv[0]) + a1[i];
}

// ---------------------------------------------------------------------------
// att[b,:,k] = softmax_over_rows(where(adj>0, e, NEG)) * adj
// ---------------------------------------------------------------------------
__global__ __launch_bounds__(256)
void softmax_kernel(const float* __restrict__ adj,
                    const float* __restrict__ e,
                    float* __restrict__ att) {
    __shared__ float sv[Nn][17];
    __shared__ float red[16][16];
    int b = blockIdx.y;
    int k = blockIdx.x * 16 + threadIdx.x;
    int tx = threadIdx.x, ty = threadIdx.y;
    const size_t base = (size_t)b * Nn * Nn;

    float m = -3.4e38f;
    for (int j = ty; j < Nn; j += 16) {
        float a = adj[base + (size_t)j * Nn + k];
        float v = (a > 0.f) ? e[base + (size_t)j * Nn + k] : NEGV;
        sv[j][tx] = v;
        m = fmaxf(m, v);
    }
    red[ty][tx] = m;
    __syncthreads();
    if (ty == 0) {
        float mm = red[0][tx];
#pragma unroll
        for (int t = 1; t < 16; t++) mm = fmaxf(mm, red[t][tx]);
        red[0][tx] = mm;
    }
    __syncthreads();
    m = red[0][tx];
    __syncthreads();

    float s = 0.f;
    for (int j = ty; j < Nn; j += 16) {
        float ev = expf(sv[j][tx] - m);
        sv[j][tx] = ev;
        s += ev;
    }
    red[ty][tx] = s;
    __syncthreads();
    if (ty == 0) {
        float ss = 0.f;
#pragma unroll
        for (int t = 0; t < 16; t++) ss += red[t][tx];
        red[0][tx] = ss;
    }
    __syncthreads();
    float inv = 1.f / red[0][tx];

    for (int j = ty; j < Nn; j += 16) {
        att[base + (size_t)j * Nn + k] =
            sv[j][tx] * inv * adj[base + (size_t)j * Nn + k];
    }
}

// ---------------------------------------------------------------------------
// Gated combine for both branches, x_new = o2 - o1.  One warp per node.
// ---------------------------------------------------------------------------
__global__ __launch_bounds__(256)
void gate_kernel(float* __restrict__ x,
                 const float* __restrict__ hp1,
                 const float* __restrict__ hp2,
                 const float* __restrict__ gwk,
                 const float* __restrict__ gbk) {
    int warp = (blockIdx.x * blockDim.x + threadIdx.x) >> 5;
    int lane = threadIdx.x & 31;
    if (warp >= Bb * Nn) return;
    float* xr = x + (size_t)warp * Dd;
    const float* h1 = hp1 + (size_t)warp * Dd;
    const float* h2 = hp2 + (size_t)warp * Dd;
    float sx = 0.f, s1 = 0.f, s2 = 0.f;
    for (int d = lane; d < Dd; d += 32) {
        float xv = xr[d];
        sx += xv * gwk[d];
        s1 += h1[d] * gwk[Dd + d];
        s2 += h2[d] * gwk[Dd + d];
    }
#pragma unroll
    for (int o = 16; o > 0; o >>= 1) {
        sx += __shfl_xor_sync(0xffffffffu, sx, o);
        s1 += __shfl_xor_sync(0xffffffffu, s1, o);
        s2 += __shfl_xor_sync(0xffffffffu, s2, o);
    }
    float gbv = gbk[0];
    float c1 = 1.f / (1.f + expf(-(sx + s1 + gbv)));
    float c2 = 1.f / (1.f + expf(-(sx + s2 + gbv)));
    for (int d = lane; d < Dd; d += 32) {
        float xv = xr[d], a = h1[d], bv = h2[d];
        xr[d] = (c2 * xv + (1.f - c2) * bv) - (c1 * xv + (1.f - c1) * a);
    }
}

// ---------------------------------------------------------------------------
// g[b,d] = sum_n x[b,n,d] * valid[b,n]
// ---------------------------------------------------------------------------
__global__ void readout_kernel(const float* __restrict__ x,
                               const float* __restrict__ valid,
                               float* __restrict__ g) {
    int b = blockIdx.x, d = threadIdx.x;
    if (d >= Dd) return;
    const float* xb = x + (size_t)b * Nn * Dd;
    const float* vb = valid + (size_t)b * Nn;
    float s = 0.f;
    for (int n = 0; n < Nn; n++) s += xb[(size_t)n * Dd + d] * vb[n];
    g[(size_t)b * Dd + d] = s;
}

// ---------------------------------------------------------------------------
// Final MLP head.
// ---------------------------------------------------------------------------
__global__ __launch_bounds__(128)
void mlp_kernel(const float* __restrict__ g,
                const float* __restrict__ w0, const float* __restrict__ b0,
                const float* __restrict__ w1, const float* __restrict__ b1,
                const float* __restrict__ w2, const float* __restrict__ b2,
                const float* __restrict__ w3, const float* __restrict__ b3,
                float* __restrict__ out) {
    int b = blockIdx.x, t = threadIdx.x;
    __shared__ float gbuf[Dd];
    __shared__ float ha[DF];
    __shared__ float hb[DF];
    __shared__ float red[DF];
    for (int i = t; i < Dd; i += DF) gbuf[i] = g[(size_t)b * Dd + i];
    __syncthreads();
    float acc = b0[t];
    for (int k = 0; k < Dd; k++) acc += gbuf[k] * w0[(size_t)k * DF + t];
    ha[t] = fmaxf(acc, 0.f);
    __syncthreads();
    acc = b1[t];
    for (int k = 0; k < DF; k++) acc += ha[k] * w1[(size_t)k * DF + t];
    hb[t] = fmaxf(acc, 0.f);
    __syncthreads();
    acc = b2[t];
    for (int k = 0; k < DF; k++) acc += hb[k] * w2[(size_t)k * DF + t];
    ha[t] = fmaxf(acc, 0.f);
    __syncthreads();
    red[t] = ha[t] * w3[t];
    __syncthreads();
    for (int s = 64; s > 0; s >>= 1) {
        if (t < s) red[t] += red[t + s];
        __syncthreads();
    }
    if (t == 0) out[b] = 1.f / (1.f + expf(-(red[0] + b3[0])));
}

// ---------------------------------------------------------------------------
extern "C" void kernel_launch(void* const* d_in, const int* in_sizes, int n_in,
                              void* d_out, int out_size) {
    const float* c_hs  = (const float*)d_in[0];
    const float* adj1  = (const float*)d_in[1];
    const float* c2    = (const float*)d_in[2];
    const float* valid = (const float*)d_in[3];
    const float* We    = (const float*)d_in[4];
    const float* Ww    = (const float*)d_in[5];
    const float* Wb    = (const float*)d_in[6];
    const float* Amat  = (const float*)d_in[7];
    const float* gw    = (const float*)d_in[8];
    const float* gb    = (const float*)d_in[9];
    const float* mu    = (const float*)d_in[10];
    const float* dv    = (const float*)d_in[11];
    const float* w0 = (const float*)d_in[12]; const float* b0 = (const float*)d_in[13];
    const float* w1 = (const float*)d_in[14]; const float* b1 = (const float*)d_in[15];
    const float* w2 = (const float*)d_in[16]; const float* b2 = (const float*)d_in[17];
    const float* w3 = (const float*)d_in[18]; const float* b3 = (const float*)d_in[19];
    float* out = (float*)d_out;

    float* base = nullptr;
    cudaGetSymbolAddress((void**)&base, g_scratch);
    float* x    = base;
    float* h    = base + BND;
    float* hA   = base + 2 * BND;
    float* hp1  = base + 3 * BND;
    float* hp2  = base + 4 * BND;
    float* g    = base + 5 * BND;
    float* e    = g + (size_t)Bb * Dd;
    float* att  = e + BNN;
    float* adj2 = att + BNN;

    int M = Bb * Nn;
    dim3 tb2(16, 16);

    // x = c_hs @ We^T
    lin_bt_tc<<<dim3(3, M / 64), 128>>>(c_hs, We, nullptr, x, M, Dd, FIN);
    // adj2 = exp(-(c2-mu)^2/dev) + adj1
    adj2_kernel<<<(unsigned)((BNN + 255) / 256), 256>>>(adj1, c2, mu, dv, adj2, BNN);

    for (int k = 0; k < LL; k++) {
        const float* Wwk = Ww + (size_t)k * Dd * Dd;
        const float* Wbk = Wb + (size_t)k * Dd;
        const float* Ak  = Amat + (size_t)k * Dd * Dd;
        const float* gwk = gw + (size_t)k * 2 * Dd;
        const float* gbk = gb + k;

        lin_bt_tc<<<dim3(3, M / 64), 128>>>(x, Wwk, Wbk, h, M, Dd, Dd);
        nn_tc<<<dim3(3, M / 64), 128>>>(h, Ak, hA, M, Dd, Dd);
        esym_tc<<<dim3(Nn / 64, Nn / 64, Bb), 128>>>(h, hA, e);

        softmax_kernel<<<dim3(Nn / 16, Bb), tb2>>>(adj1, e, att);
        atth_tc<<<dim3(3, Nn / 64, Bb), 128>>>(att, h, hp1);

        softmax_kernel<<<dim3(Nn / 16, Bb), tb2>>>(adj2, e, att);
        atth_tc<<<dim3(3, Nn / 64, Bb), 128>>>(att, h, hp2);

        gate_kernel<<<(Bb * Nn) / 8, 256>>>(x, hp1, hp2, gwk, gbk);
    }

    readout_kernel<<<Bb, 160>>>(x, valid, g);
    mlp_kernel<<<Bb, DF>>>(g, w0, b0, w1, b1, w2, b2, w3, b3, out);
}

// round 7
// speedup vs baseline: 1.2319x; 1.1497x over previous
#include <cuda_runtime.h>
#include <cuda_bf16.h>
#include <math.h>

#define Bb   32
#define Nn   512
#define FIN  74
#define Dd   140
#define DF   128
#define LL   4
#define NEGV (-9e15f)

#define BNDc (Bb*Nn*Dd)     // 2,293,760
#define BNNc (Bb*Nn*Nn)     // 8,388,608
#define CHSc (Bb*Nn*FIN)    // 1,212,416
#define WEc  (Dd*FIN)       // 10,360
#define WWc  (LL*Dd*Dd)     // 78,400

typedef unsigned short ushort_t;
typedef unsigned int   uint_t;

// fp32 scratch: x, hp1, hp2, e, adj2, g
__device__ float g_f32[3ull*BNDc + 2ull*BNNc + Bb*Dd + 256];
// bf16 scratch: xhi,xlo,hhi,hlo,hAhi,hAlo,hThi,hTlo, atthi,attlo, chs, We, Ww, AT
__device__ ushort_t g_bf[8ull*BNDc + 2ull*BNNc + 2ull*CHSc + 2ull*WEc + 4ull*WWc + 256];

// ---------------------------------------------------------------------------
// bf16 helpers
// ---------------------------------------------------------------------------
__device__ __forceinline__ ushort_t f2bf(float v) {
    __nv_bfloat16 b = __float2bfloat16(v);
    return ((__nv_bfloat16_raw)b).x;
}
__device__ __forceinline__ float bfbits2f(ushort_t u) {
    __nv_bfloat16_raw r; r.x = u;
    return __bfloat162float(__nv_bfloat16(r));
}

__device__ __forceinline__ void ldsm4(uint_t r[4], const ushort_t* p) {
    uint_t a = (uint_t)__cvta_generic_to_shared(p);
    asm volatile("ldmatrix.sync.aligned.m8n8.x4.shared.b16 {%0,%1,%2,%3}, [%4];"
                 : "=r"(r[0]), "=r"(r[1]), "=r"(r[2]), "=r"(r[3]) : "r"(a));
}

__device__ __forceinline__ void mma_bf16(float c[4], const uint_t a[4],
                                         const uint_t b[2]) {
    asm volatile(
        "mma.sync.aligned.m16n8k16.row.col.f32.bf16.bf16.f32 "
        "{%0,%1,%2,%3}, {%4,%5,%6,%7}, {%8,%9}, {%0,%1,%2,%3};\n"
        : "+f"(c[0]), "+f"(c[1]), "+f"(c[2]), "+f"(c[3])
        : "r"(a[0]), "r"(a[1]), "r"(a[2]), "r"(a[3]), "r"(b[0]), "r"(b[1]));
}

#define SLD 40  // smem leading dim (ushorts): 80B rows -> 16B-aligned ldmatrix, conflict-free

// warp computes 32x32 over one BK=32 smem tile (2 k16 steps, 3-mma bf16 split)
__device__ __forceinline__ void mma_tile(const ushort_t* sAhi, const ushort_t* sAlo,
                                         const ushort_t* sBhi, const ushort_t* sBlo,
                                         int warp_m, int warp_n, int lane,
                                         float acc[2][4][4]) {
    int arow = lane & 15, asel = (lane >> 4) << 3;
    int brow = (lane & 7) + ((lane >> 4) & 1) * 8, bsel = ((lane >> 3) & 1) * 8;
#pragma unroll
    for (int kk = 0; kk < 32; kk += 16) {
        uint_t ah[2][4], al[2][4];
#pragma unroll
        for (int mf = 0; mf < 2; mf++) {
            int off = (warp_m + mf * 16 + arow) * SLD + kk + asel;
            ldsm4(ah[mf], sAhi + off);
            ldsm4(al[mf], sAlo + off);
        }
        uint_t bh[4][2], bl[4][2];
#pragma unroll
        for (int q = 0; q < 2; q++) {
            int off = (warp_n + q * 16 + brow) * SLD + kk + bsel;
            uint_t t[4];
            ldsm4(t, sBhi + off);
            bh[2 * q][0] = t[0]; bh[2 * q][1] = t[1];
            bh[2 * q + 1][0] = t[2]; bh[2 * q + 1][1] = t[3];
            ldsm4(t, sBlo + off);
            bl[2 * q][0] = t[0]; bl[2 * q][1] = t[1];
            bl[2 * q + 1][0] = t[2]; bl[2 * q + 1][1] = t[3];
        }
#pragma unroll
        for (int mf = 0; mf < 2; mf++)
#pragma unroll
            for (int nf = 0; nf < 4; nf++) {
                mma_bf16(acc[mf][nf], ah[mf], bh[nf]);
                mma_bf16(acc[mf][nf], ah[mf], bl[nf]);
                mma_bf16(acc[mf][nf], al[mf], bh[nf]);
            }
    }
}

// ---------------------------------------------------------------------------
// Generic planes GEMM: C[M,Nc] = A[M,K] * B[Nc,K]^T (+bias)
// MODE bits: 1=write f32, 2=write planes, 4=write T-planes (h only), 8=relu, 16=bias
// ---------------------------------------------------------------------------
template<int MODE>
__global__ __launch_bounds__(128)
void gemm_bf16(const ushort_t* __restrict__ Ahi_g, const ushort_t* __restrict__ Alo_g,
               const ushort_t* __restrict__ Bhi_g, const ushort_t* __restrict__ Blo_g,
               const float* __restrict__ bias,
               float* __restrict__ Cf, ushort_t* __restrict__ Chi,
               ushort_t* __restrict__ Clo,
               ushort_t* __restrict__ CThi, ushort_t* __restrict__ CTlo,
               int M, int Nc, int K,
               size_t strA, size_t strB, size_t strC) {
    __shared__ ushort_t sAhi[64 * SLD], sAlo[64 * SLD], sBhi[64 * SLD], sBlo[64 * SLD];
    int z = blockIdx.z;
    Ahi_g += z * strA; Alo_g += z * strA;
    Bhi_g += z * strB; Blo_g += z * strB;
    int bm = blockIdx.y * 64, bn = blockIdx.x * 64;
    int tid = threadIdx.x, lane = tid & 31, wid = tid >> 5;
    int warp_m = (wid >> 1) * 32, warp_n = (wid & 1) * 32;
    float acc[2][4][4] = {};
    int kiter = (K + 31) / 32;
    for (int kt = 0; kt < kiter; kt++) {
        int k0 = kt * 32;
#pragma unroll
        for (int i = 0; i < 8; i++) {
            int idx = tid + i * 128;
            int m = idx >> 4, kp = idx & 15;
            int k = k0 + 2 * kp;
            uint_t avh = 0, avl = 0, bvh = 0, bvl = 0;
            if (k < K) {
                size_t ga = (size_t)(bm + m) * K + k;
                avh = *(const uint_t*)(Ahi_g + ga);
                avl = *(const uint_t*)(Alo_g + ga);
                if (bn + m < Nc) {
                    size_t gb = (size_t)(bn + m) * K + k;
                    bvh = *(const uint_t*)(Bhi_g + gb);
                    bvl = *(const uint_t*)(Blo_g + gb);
                }
            }
            *(uint_t*)&sAhi[m * SLD + 2 * kp] = avh;
            *(uint_t*)&sAlo[m * SLD + 2 * kp] = avl;
            *(uint_t*)&sBhi[m * SLD + 2 * kp] = bvh;
            *(uint_t*)&sBlo[m * SLD + 2 * kp] = bvl;
        }
        __syncthreads();
        mma_tile(sAhi, sAlo, sBhi, sBlo, warp_m, warp_n, lane, acc);
        __syncthreads();
    }
    int quad = lane >> 2, tq = lane & 3;
#pragma unroll
    for (int mf = 0; mf < 2; mf++)
#pragma unroll
        for (int nf = 0; nf < 4; nf++) {
            int r0 = bm + warp_m + mf * 16 + quad;
            int c0 = bn + warp_n + nf * 8 + 2 * tq;
#pragma unroll
            for (int v = 0; v < 4; v++) {
                int r = r0 + (v >> 1) * 8, c = c0 + (v & 1);
                if (c >= Nc) continue;
                float val = acc[mf][nf][v];
                if (MODE & 16) val += bias[c];
                if (MODE & 8) val = fmaxf(val, 0.f);
                size_t oi = (size_t)z * strC + (size_t)r * Nc + c;
                if (MODE & 1) Cf[oi] = val;
                if (MODE & 2) {
                    ushort_t h = f2bf(val);
                    Chi[oi] = h;
                    Clo[oi] = f2bf(val - bfbits2f(h));
                }
                if (MODE & 4) {
                    // T-planes for h: [b][Dd][Nn], r = b*512+n
                    size_t ti = ((size_t)(r >> 9) * Dd + c) * Nn + (r & 511);
                    ushort_t h = f2bf(val);
                    CThi[ti] = h;
                    CTlo[ti] = f2bf(val - bfbits2f(h));
                }
            }
        }
}

// ---------------------------------------------------------------------------
// esym: E[b,j,k] = hA_j.h_k + h_j.hA_k as one planes-GEMM with concat K=280
// ---------------------------------------------------------------------------
__global__ __launch_bounds__(128)
void esym_bf16(const ushort_t* __restrict__ Hhi, const ushort_t* __restrict__ Hlo,
               const ushort_t* __restrict__ Phi, const ushort_t* __restrict__ Plo,
               float* __restrict__ E) {
    __shared__ ushort_t sAhi[64 * SLD], sAlo[64 * SLD], sBhi[64 * SLD], sBlo[64 * SLD];
    int b = blockIdx.z;
    size_t boff = (size_t)b * Nn * Dd;
    const ushort_t* Hh = Hhi + boff; const ushort_t* Hl = Hlo + boff;
    const ushort_t* Ph = Phi + boff; const ushort_t* Pl = Plo + boff;
    float* Eb = E + (size_t)b * Nn * Nn;
    int bm = blockIdx.y * 64, bn = blockIdx.x * 64;
    int tid = threadIdx.x, lane = tid & 31, wid = tid >> 5;
    int warp_m = (wid >> 1) * 32, warp_n = (wid & 1) * 32;
    float acc[2][4][4] = {};
    for (int kt = 0; kt < 9; kt++) {  // K=280 padded to 288
        int k0 = kt * 32;
#pragma unroll
        for (int i = 0; i < 8; i++) {
            int idx = tid + i * 128;
            int m = idx >> 4, kp = idx & 15;
            int kg = k0 + 2 * kp;
            uint_t avh = 0, avl = 0, bvh = 0, bvl = 0;
            if (kg < 2 * Dd) {
                const ushort_t *pah, *pal, *pbh, *pbl;
                int ka;
                if (kg < Dd) { pah = Ph; pal = Pl; pbh = Hh; pbl = Hl; ka = kg; }
                else         { pah = Hh; pal = Hl; pbh = Ph; pbl = Pl; ka = kg - Dd; }
                size_t ga = (size_t)(bm + m) * Dd + ka;
                size_t gb = (size_t)(bn + m) * Dd + ka;
                avh = *(const uint_t*)(pah + ga);
                avl = *(const uint_t*)(pal + ga);
                bvh = *(const uint_t*)(pbh + gb);
                bvl = *(const uint_t*)(pbl + gb);
            }
            *(uint_t*)&sAhi[m * SLD + 2 * kp] = avh;
            *(uint_t*)&sAlo[m * SLD + 2 * kp] = avl;
            *(uint_t*)&sBhi[m * SLD + 2 * kp] = bvh;
            *(uint_t*)&sBlo[m * SLD + 2 * kp] = bvl;
        }
        __syncthreads();
        mma_tile(sAhi, sAlo, sBhi, sBlo, warp_m, warp_n, lane, acc);
        __syncthreads();
    }
    int quad = lane >> 2, tq = lane & 3;
#pragma unroll
    for (int mf = 0; mf < 2; mf++)
#pragma unroll
        for (int nf = 0; nf < 4; nf++) {
            int r0 = bm + warp_m + mf * 16 + quad;
            int c0 = bn + warp_n + nf * 8 + 2 * tq;
#pragma unroll
            for (int v = 0; v < 4; v++)
                Eb[(size_t)(r0 + (v >> 1) * 8) * Nn + c0 + (v & 1)] = acc[mf][nf][v];
        }
}

// ---------------------------------------------------------------------------
// conversion kernels (run once per call, out of the hot loop)
// ---------------------------------------------------------------------------
__global__ void cvt_kernel(const float* __restrict__ src, ushort_t* __restrict__ hi,
                           ushort_t* __restrict__ lo, int n) {
    int i = blockIdx.x * blockDim.x + threadIdx.x;
    if (i >= n) return;
    float v = src[i];
    ushort_t h = f2bf(v);
    hi[i] = h;
    lo[i] = f2bf(v - bfbits2f(h));
}

// transpose-convert Amat: out[layer][c][r] = in[layer][r][c]
__global__ void cvtT_kernel(const float* __restrict__ src, ushort_t* __restrict__ hi,
                            ushort_t* __restrict__ lo, int n) {
    int i = blockIdx.x * blockDim.x + threadIdx.x;
    if (i >= n) return;
    int layer = i / (Dd * Dd);
    int rem = i - layer * Dd * Dd;
    int r = rem / Dd, c = rem - r * Dd;
    float v = src[i];
    int o = layer * Dd * Dd + c * Dd + r;
    ushort_t h = f2bf(v);
    hi[o] = h;
    lo[o] = f2bf(v - bfbits2f(h));
}

// ---------------------------------------------------------------------------
// adj2 = exp(-(c2 - mu)^2 / dev) + adj1
// ---------------------------------------------------------------------------
__global__ void adj2_kernel(const float* __restrict__ a1,
                            const float* __restrict__ c2,
                            const float* __restrict__ mu,
                            const float* __restrict__ dv,
                            float* __restrict__ adj2, size_t total) {
    size_t i = (size_t)blockIdx.x * blockDim.x + threadIdx.x;
    if (i >= total) return;
    float d = c2[i] - mu[0];
    adj2[i] = expf(-d * d / dv[0]) + a1[i];
}

// ---------------------------------------------------------------------------
// softmax over rows (axis=1) -> att planes (bf16 hi/lo), fused *adj.
// ---------------------------------------------------------------------------
__global__ __launch_bounds__(256)
void softmax_kernel(const float* __restrict__ adj,
                    const float* __restrict__ e,
                    ushort_t* __restrict__ atthi,
                    ushort_t* __restrict__ attlo) {
    __shared__ float sv[Nn][17];
    __shared__ float red[16][16];
    int b = blockIdx.y;
    int k = blockIdx.x * 16 + threadIdx.x;
    int tx = threadIdx.x, ty = threadIdx.y;
    const size_t base = (size_t)b * Nn * Nn;

    float m = -3.4e38f;
    for (int j = ty; j < Nn; j += 16) {
        float a = adj[base + (size_t)j * Nn + k];
        float v = (a > 0.f) ? e[base + (size_t)j * Nn + k] : NEGV;
        sv[j][tx] = v;
        m = fmaxf(m, v);
    }
    red[ty][tx] = m;
    __syncthreads();
    if (ty == 0) {
        float mm = red[0][tx];
#pragma unroll
        for (int t = 1; t < 16; t++) mm = fmaxf(mm, red[t][tx]);
        red[0][tx] = mm;
    }
    __syncthreads();
    m = red[0][tx];
    __syncthreads();

    float s = 0.f;
    for (int j = ty; j < Nn; j += 16) {
        float ev = expf(sv[j][tx] - m);
        sv[j][tx] = ev;
        s += ev;
    }
    red[ty][tx] = s;
    __syncthreads();
    if (ty == 0) {
        float ss = 0.f;
#pragma unroll
        for (int t = 0; t < 16; t++) ss += red[t][tx];
        red[0][tx] = ss;
    }
    __syncthreads();
    float inv = 1.f / red[0][tx];

    for (int j = ty; j < Nn; j += 16) {
        size_t idx = base + (size_t)j * Nn + k;
        float v = sv[j][tx] * inv * adj[idx];
        ushort_t h = f2bf(v);
        atthi[idx] = h;
        attlo[idx] = f2bf(v - bfbits2f(h));
    }
}

// ---------------------------------------------------------------------------
// Gated combine, writes new x (fp32) + x planes. One warp per node.
// ---------------------------------------------------------------------------
__global__ __launch_bounds__(256)
void gate_kernel(float* __restrict__ x,
                 ushort_t* __restrict__ xhi, ushort_t* __restrict__ xlo,
                 const float* __restrict__ hp1,
                 const float* __restrict__ hp2,
                 const float* __restrict__ gwk,
                 const float* __restrict__ gbk) {
    int warp = (blockIdx.x * blockDim.x + threadIdx.x) >> 5;
    int lane = threadIdx.x & 31;
    if (warp >= Bb * Nn) return;
    size_t roff = (size_t)warp * Dd;
    float* xr = x + roff;
    const float* h1 = hp1 + roff;
    const float* h2 = hp2 + roff;
    float sx = 0.f, s1 = 0.f, s2 = 0.f;
    for (int d = lane; d < Dd; d += 32) {
        float xv = xr[d];
        sx += xv * gwk[d];
        s1 += h1[d] * gwk[Dd + d];
        s2 += h2[d] * gwk[Dd + d];
    }
#pragma unroll
    for (int o = 16; o > 0; o >>= 1) {
        sx += __shfl_xor_sync(0xffffffffu, sx, o);
        s1 += __shfl_xor_sync(0xffffffffu, s1, o);
        s2 += __shfl_xor_sync(0xffffffffu, s2, o);
    }
    float gbv = gbk[0];
    float c1 = 1.f / (1.f + expf(-(sx + s1 + gbv)));
    float c2 = 1.f / (1.f + expf(-(sx + s2 + gbv)));
    for (int d = lane; d < Dd; d += 32) {
        float xv = xr[d], a = h1[d], bv = h2[d];
        float nv = (c2 * xv + (1.f - c2) * bv) - (c1 * xv + (1.f - c1) * a);
        xr[d] = nv;
        ushort_t h = f2bf(nv);
        xhi[roff + d] = h;
        xlo[roff + d] = f2bf(nv - bfbits2f(h));
    }
}

// ---------------------------------------------------------------------------
// g[b,d] = sum_n x[b,n,d] * valid[b,n]
// ---------------------------------------------------------------------------
__global__ void readout_kernel(const float* __restrict__ x,
                               const float* __restrict__ valid,
                               float* __restrict__ g) {
    int b = blockIdx.x, d = threadIdx.x;
    if (d >= Dd) return;
    const float* xb = x + (size_t)b * Nn * Dd;
    const float* vb = valid + (size_t)b * Nn;
    float s = 0.f;
    for (int n = 0; n < Nn; n++) s += xb[(size_t)n * Dd + d] * vb[n];
    g[(size_t)b * Dd + d] = s;
}

// ---------------------------------------------------------------------------
// Final MLP head.
// ---------------------------------------------------------------------------
__global__ __launch_bounds__(128)
void mlp_kernel(const float* __restrict__ g,
                const float* __restrict__ w0, const float* __restrict__ b0,
                const float* __restrict__ w1, const float* __restrict__ b1,
                const float* __restrict__ w2, const float* __restrict__ b2,
                const float* __restrict__ w3, const float* __restrict__ b3,
                float* __restrict__ out) {
    int b = blockIdx.x, t = threadIdx.x;
    __shared__ float gbuf[Dd];
    __shared__ float ha[DF];
    __shared__ float hb[DF];
    __shared__ float red[DF];
    for (int i = t; i < Dd; i += DF) gbuf[i] = g[(size_t)b * Dd + i];
    __syncthreads();
    float acc = b0[t];
    for (int k = 0; k < Dd; k++) acc += gbuf[k] * w0[(size_t)k * DF + t];
    ha[t] = fmaxf(acc, 0.f);
    __syncthreads();
    acc = b1[t];
    for (int k = 0; k < DF; k++) acc += ha[k] * w1[(size_t)k * DF + t];
    hb[t] = fmaxf(acc, 0.f);
    __syncthreads();
    acc = b2[t];
    for (int k = 0; k < DF; k++) acc += hb[k] * w2[(size_t)k * DF + t];
    ha[t] = fmaxf(acc, 0.f);
    __syncthreads();
    red[t] = ha[t] * w3[t];
    __syncthreads();
    for (int s = 64; s > 0; s >>= 1) {
        if (t < s) red[t] += red[t + s];
        __syncthreads();
    }
    if (t == 0) out[b] = 1.f / (1.f + expf(-(red[0] + b3[0])));
}

// ---------------------------------------------------------------------------
extern "C" void kernel_launch(void* const* d_in, const int* in_sizes, int n_in,
                              void* d_out, int out_size) {
    const float* c_hs  = (const float*)d_in[0];
    const float* adj1  = (const float*)d_in[1];
    const float* c2    = (const float*)d_in[2];
    const float* valid = (const float*)d_in[3];
    const float* We    = (const float*)d_in[4];
    const float* Ww    = (const float*)d_in[5];
    const float* Wb    = (const float*)d_in[6];
    const float* Amat  = (const float*)d_in[7];
    const float* gw    = (const float*)d_in[8];
    const float* gb    = (const float*)d_in[9];
    const float* mu    = (const float*)d_in[10];
    const float* dv    = (const float*)d_in[11];
    const float* w0 = (const float*)d_in[12]; const float* b0 = (const float*)d_in[13];
    const float* w1 = (const float*)d_in[14]; const float* b1 = (const float*)d_in[15];
    const float* w2 = (const float*)d_in[16]; const float* b2 = (const float*)d_in[17];
    const float* w3 = (const float*)d_in[18]; const float* b3 = (const float*)d_in[19];
    float* out = (float*)d_out;

    float* fbase = nullptr;
    cudaGetSymbolAddress((void**)&fbase, g_f32);
    float* x    = fbase;
    float* hp1  = fbase + (size_t)BNDc;
    float* hp2  = fbase + 2ull * BNDc;
    float* e    = fbase + 3ull * BNDc;
    float* adj2 = e + (size_t)BNNc;
    float* g    = adj2 + (size_t)BNNc;

    ushort_t* ubase = nullptr;
    cudaGetSymbolAddress((void**)&ubase, g_bf);
    ushort_t* xhi  = ubase;
    ushort_t* xlo  = ubase + 1ull * BNDc;
    ushort_t* hhi  = ubase + 2ull * BNDc;
    ushort_t* hlo  = ubase + 3ull * BNDc;
    ushort_t* hAhi = ubase + 4ull * BNDc;
    ushort_t* hAlo = ubase + 5ull * BNDc;
    ushort_t* hThi = ubase + 6ull * BNDc;
    ushort_t* hTlo = ubase + 7ull * BNDc;
    ushort_t* atthi = ubase + 8ull * BNDc;
    ushort_t* attlo = atthi + (size_t)BNNc;
    ushort_t* chshi = attlo + (size_t)BNNc;
    ushort_t* chslo = chshi + (size_t)CHSc;
    ushort_t* Wehi  = chslo + (size_t)CHSc;
    ushort_t* Welo  = Wehi + WEc;
    ushort_t* Wwhi  = Welo + WEc;
    ushort_t* Wwlo  = Wwhi + WWc;
    ushort_t* AThi  = Wwlo + WWc;
    ushort_t* ATlo  = AThi + WWc;

    int M = Bb * Nn;
    dim3 tb2(16, 16);

    // one-time conversions (per call; cheap, memory-bound)
    cvt_kernel<<<(CHSc + 255) / 256, 256>>>(c_hs, chshi, chslo, CHSc);
    cvt_kernel<<<(WEc + 255) / 256, 256>>>(We, Wehi, Welo, WEc);
    cvt_kernel<<<(WWc + 255) / 256, 256>>>(Ww, Wwhi, Wwlo, WWc);
    cvtT_kernel<<<(WWc + 255) / 256, 256>>>(Amat, AThi, ATlo, WWc);
    adj2_kernel<<<(unsigned)(((size_t)BNNc + 255) / 256), 256>>>(adj1, c2, mu, dv, adj2, BNNc);

    // embed: x = c_hs @ We^T  (f32 + planes)
    gemm_bf16<3><<<dim3(3, M / 64, 1), 128>>>(
        chshi, chslo, Wehi, Welo, nullptr,
        x, xhi, xlo, nullptr, nullptr, M, Dd, FIN, 0, 0, 0);

    for (int k = 0; k < LL; k++) {
        const float* Wbk = Wb + (size_t)k * Dd;
        const float* gwk = gw + (size_t)k * 2 * Dd;
        const float* gbk = gb + k;
        size_t woff = (size_t)k * Dd * Dd;

        // h = x @ Ww^T + Wb   (planes + T-planes, bias)
        gemm_bf16<2 | 4 | 16><<<dim3(3, M / 64, 1), 128>>>(
            xhi, xlo, Wwhi + woff, Wwlo + woff, Wbk,
            nullptr, hhi, hlo, hThi, hTlo, M, Dd, Dd, 0, 0, 0);

        // hA = h @ A          (planes)
        gemm_bf16<2><<<dim3(3, M / 64, 1), 128>>>(
            hhi, hlo, AThi + woff, ATlo + woff, nullptr,
            nullptr, hAhi, hAlo, nullptr, nullptr, M, Dd, Dd, 0, 0, 0);

        // e = hA h^T + h hA^T (f32)
        esym_bf16<<<dim3(Nn / 64, Nn / 64, Bb), 128>>>(hhi, hlo, hAhi, hAlo, e);

        // branch 1 (adj1)
        softmax_kernel<<<dim3(Nn / 16, Bb), tb2>>>(adj1, e, atthi, attlo);
        gemm_bf16<1 | 8><<<dim3(3, Nn / 64, Bb), 128>>>(
            atthi, attlo, hThi, hTlo, nullptr,
            hp1, nullptr, nullptr, nullptr, nullptr, Nn, Dd, Nn,
            (size_t)Nn * Nn, (size_t)Dd * Nn, (size_t)Nn * Dd);

        // branch 2 (adj2)
        softmax_kernel<<<dim3(Nn / 16, Bb), tb2>>>(adj2, e, atthi, attlo);
        gemm_bf16<1 | 8><<<dim3(3, Nn / 64, Bb), 128>>>(
            atthi, attlo, hThi, hTlo, nullptr,
            hp2, nullptr, nullptr, nullptr, nullptr, Nn, Dd, Nn,
            (size_t)Nn * Nn, (size_t)Dd * Nn, (size_t)Nn * Dd);

        gate_kernel<<<(Bb * Nn) / 8, 256>>>(x, xhi, xlo, hp1, hp2, gwk, gbk);
    }

    readout_kernel<<<Bb, 160>>>(x, valid, g);
    mlp_kernel<<<Bb, DF>>>(g, w0, b0, w1, b1, w2, b2, w3, b3, out);
}

// round 8
// speedup vs baseline: 2.2763x; 1.8478x over previous
#include <cuda_runtime.h>
#include <cuda_bf16.h>
#include <math.h>

#define Bb   32
#define Nn   512
#define FIN  74
#define Dd   140
#define DF   128
#define LL   4
#define NEGV (-9e15f)

#define KPD  160   // padded Dd (K-major plane row length)
#define KPF  96    // padded FIN
#define NPD  192   // padded Dd rows for B-side operands

#define BNDc (Bb*Nn*Dd)          // 2,293,760 (f32 x / hp per branch)
#define BNNc (Bb*Nn*Nn)          // 8,388,608

// plane sizes (ushorts, per hi or lo)
#define XPLs   (Bb*Nn*KPD)       // 2,621,440
#define HTs    (Bb*NPD*Nn)       // 3,145,728
#define ATTs   (Bb*2*Nn*Nn)      // 16,777,216
#define CHSs   (Bb*Nn*KPF)       // 1,572,864
#define WEs    (NPD*KPF)         // 18,432
#define WWs    (LL*NPD*KPD)      // 122,880

typedef unsigned short ushort_t;
typedef unsigned int   uint_t;

// fp32 scratch: x, hp[b][br], e, adj2, g
__device__ float g_f32[(size_t)BNDc + 2ull*BNDc + 2ull*BNNc + Bb*Dd + 256];
// bf16 planes (hi then lo for each)
__device__ ushort_t g_bf[2ull*(3ull*XPLs + HTs + ATTs + CHSs + WEs + 2ull*WWs) + 256];

// ---------------------------------------------------------------------------
__device__ __forceinline__ ushort_t f2bf(float v) {
    __nv_bfloat16 b = __float2bfloat16(v);
    return ((__nv_bfloat16_raw)b).x;
}
__device__ __forceinline__ float bfbits2f(ushort_t u) {
    __nv_bfloat16_raw r; r.x = u;
    return __bfloat162float(__nv_bfloat16(r));
}

__device__ __forceinline__ void ldsm4(uint_t r[4], const ushort_t* p) {
    uint_t a = (uint_t)__cvta_generic_to_shared(p);
    asm volatile("ldmatrix.sync.aligned.m8n8.x4.shared.b16 {%0,%1,%2,%3}, [%4];"
                 : "=r"(r[0]), "=r"(r[1]), "=r"(r[2]), "=r"(r[3]) : "r"(a));
}

__device__ __forceinline__ void mma_bf16(float c[4], const uint_t a[4],
                                         const uint_t b[2]) {
    asm volatile(
        "mma.sync.aligned.m16n8k16.row.col.f32.bf16.bf16.f32 "
        "{%0,%1,%2,%3}, {%4,%5,%6,%7}, {%8,%9}, {%0,%1,%2,%3};\n"
        : "+f"(c[0]), "+f"(c[1]), "+f"(c[2]), "+f"(c[3])
        : "r"(a[0]), "r"(a[1]), "r"(a[2]), "r"(a[3]), "r"(b[0]), "r"(b[1]));
}

__device__ __forceinline__ void cpa16(ushort_t* dst, const ushort_t* src) {
    uint_t d = (uint_t)__cvta_generic_to_shared(dst);
    asm volatile("cp.async.cg.shared.global [%0], [%1], 16;" :: "r"(d), "l"(src));
}
#define CP_COMMIT() asm volatile("cp.async.commit_group;" ::: "memory")
#define CP_WAIT0()  asm volatile("cp.async.wait_group 0;" ::: "memory")

#define SLD 40  // smem row length (ushorts): 80B rows, 16B aligned, conflict-free

// warp computes 32x32 over one BK=32 smem tile (2 k16 steps, 3-mma bf16 split)
__device__ __forceinline__ void mma_tile(const ushort_t* sAhi, const ushort_t* sAlo,
                                         const ushort_t* sBhi, const ushort_t* sBlo,
                                         int warp_m, int warp_n, int lane,
                                         float acc[2][4][4]) {
    int arow = lane & 15, asel = (lane >> 4) << 3;
    int brow = (lane & 7) + ((lane >> 4) & 1) * 8, bsel = ((lane >> 3) & 1) * 8;
#pragma unroll
    for (int kk = 0; kk < 32; kk += 16) {
        uint_t ah[2][4], al[2][4];
#pragma unroll
        for (int mf = 0; mf < 2; mf++) {
            int off = (warp_m + mf * 16 + arow) * SLD + kk + asel;
            ldsm4(ah[mf], sAhi + off);
            ldsm4(al[mf], sAlo + off);
        }
        uint_t bh[4][2], bl[4][2];
#pragma unroll
        for (int q = 0; q < 2; q++) {
            int off = (warp_n + q * 16 + brow) * SLD + kk + bsel;
            uint_t t[4];
            ldsm4(t, sBhi + off);
            bh[2 * q][0] = t[0]; bh[2 * q][1] = t[1];
            bh[2 * q + 1][0] = t[2]; bh[2 * q + 1][1] = t[3];
            ldsm4(t, sBlo + off);
            bl[2 * q][0] = t[0]; bl[2 * q][1] = t[1];
            bl[2 * q + 1][0] = t[2]; bl[2 * q + 1][1] = t[3];
        }
#pragma unroll
        for (int mf = 0; mf < 2; mf++)
#pragma unroll
            for (int nf = 0; nf < 4; nf++) {
                mma_bf16(acc[mf][nf], ah[mf], bh[nf]);
                mma_bf16(acc[mf][nf], ah[mf], bl[nf]);
                mma_bf16(acc[mf][nf], al[mf], bh[nf]);
            }
    }
}

// ---------------------------------------------------------------------------
// cp.async double-buffered planes GEMM: C[.,Nc] = A[.,K] * B[rows,K]^T (+bias)
// All K loads unguarded: K multiple of 32, rows padded (NPD / full). 16B aligned.
// MODE bits: 1=f32 out, 2=planes out, 4=hT planes out, 8=relu, 16=bias
// HALFZ: B batch index = z>>1 (for branch-batched atth)
// ---------------------------------------------------------------------------
template<int MODE, int HALFZ>
__global__ __launch_bounds__(128)
void gemm_ca(const ushort_t* __restrict__ Ahi, const ushort_t* __restrict__ Alo,
             const ushort_t* __restrict__ Bhi, const ushort_t* __restrict__ Blo,
             const float* __restrict__ bias,
             float* __restrict__ Cf, ushort_t* __restrict__ Chi,
             ushort_t* __restrict__ Clo,
             ushort_t* __restrict__ CThi, ushort_t* __restrict__ CTlo,
             int Nc, int K, int KA, int KB, int NcP,
             size_t strA, size_t strB, size_t strC) {
    __shared__ ushort_t smem[2][4][64 * SLD];
    int z = blockIdx.z;
    Ahi += (size_t)z * strA; Alo += (size_t)z * strA;
    size_t bz = HALFZ ? (size_t)(z >> 1) : (size_t)z;
    Bhi += bz * strB; Blo += bz * strB;
    int bm = blockIdx.y * 64, bn = blockIdx.x * 64;
    int tid = threadIdx.x, lane = tid & 31, wid = tid >> 5;
    int warp_m = (wid >> 1) * 32, warp_n = (wid & 1) * 32;
    float acc[2][4][4] = {};

    auto issue_tile = [&](int kt, int st) {
        int k0 = kt * 32;
#pragma unroll
        for (int c = 0; c < 8; c++) {
            int w = ((c & 1) << 7) | tid;
            int m = w >> 2, kc = (w & 3) << 3;
            const ushort_t* src;
            if ((c >> 1) == 0)      src = Ahi + (size_t)(bm + m) * KA + k0 + kc;
            else if ((c >> 1) == 1) src = Alo + (size_t)(bm + m) * KA + k0 + kc;
            else if ((c >> 1) == 2) src = Bhi + (size_t)(bn + m) * KB + k0 + kc;
            else                    src = Blo + (size_t)(bn + m) * KB + k0 + kc;
            cpa16(&smem[st][c >> 1][m * SLD + kc], src);
        }
        CP_COMMIT();
    };

    int kiter = K >> 5;
    issue_tile(0, 0);
    for (int kt = 0; kt < kiter; kt++) {
        CP_WAIT0();
        __syncthreads();
        if (kt + 1 < kiter) issue_tile(kt + 1, (kt + 1) & 1);
        mma_tile(smem[kt & 1][0], smem[kt & 1][1], smem[kt & 1][2], smem[kt & 1][3],
                 warp_m, warp_n, lane, acc);
    }

    int quad = lane >> 2, tq = lane & 3;
#pragma unroll
    for (int mf = 0; mf < 2; mf++)
#pragma unroll
        for (int nf = 0; nf < 4; nf++) {
            int r0 = bm + warp_m + mf * 16 + quad;
            int c0 = bn + warp_n + nf * 8 + 2 * tq;
#pragma unroll
            for (int v = 0; v < 4; v++) {
                int r = r0 + (v >> 1) * 8, c = c0 + (v & 1);
                if (c >= Nc) continue;
                float val = acc[mf][nf][v];
                if (MODE & 16) val += bias[c];
                if (MODE & 8) val = fmaxf(val, 0.f);
                if (MODE & 1) Cf[(size_t)z * strC + (size_t)r * Nc + c] = val;
                if (MODE & 2) {
                    size_t oi = (size_t)z * strC + (size_t)r * NcP + c;
                    ushort_t h = f2bf(val);
                    Chi[oi] = h;
                    Clo[oi] = f2bf(val - bfbits2f(h));
                }
                if (MODE & 4) {
                    size_t ti = (size_t)(r >> 9) * (NPD * Nn) + (size_t)c * Nn + (r & 511);
                    ushort_t h = f2bf(val);
                    CThi[ti] = h;
                    CTlo[ti] = f2bf(val - bfbits2f(h));
                }
            }
        }
}

// ---------------------------------------------------------------------------
// esym: E[b,j,k] = hA_j.h_k + h_j.hA_k, concat K = 2*KPD = 320 (10 k-tiles)
// ---------------------------------------------------------------------------
__global__ __launch_bounds__(128)
void esym_ca(const ushort_t* __restrict__ Hhi, const ushort_t* __restrict__ Hlo,
             const ushort_t* __restrict__ Phi, const ushort_t* __restrict__ Plo,
             float* __restrict__ E) {
    __shared__ ushort_t smem[2][4][64 * SLD];
    int b = blockIdx.z;
    size_t boff = (size_t)b * Nn * KPD;
    const ushort_t* Hh = Hhi + boff; const ushort_t* Hl = Hlo + boff;
    const ushort_t* Ph = Phi + boff; const ushort_t* Pl = Plo + boff;
    float* Eb = E + (size_t)b * Nn * Nn;
    int bm = blockIdx.y * 64, bn = blockIdx.x * 64;
    int tid = threadIdx.x, lane = tid & 31, wid = tid >> 5;
    int warp_m = (wid >> 1) * 32, warp_n = (wid & 1) * 32;
    float acc[2][4][4] = {};

    auto issue_tile = [&](int kt, int st) {
        const ushort_t* pAh = (kt < 5) ? Ph : Hh;
        const ushort_t* pAl = (kt < 5) ? Pl : Hl;
        const ushort_t* pBh = (kt < 5) ? Hh : Ph;
        const ushort_t* pBl = (kt < 5) ? Hl : Pl;
        int k0 = ((kt < 5) ? kt : kt - 5) * 32;
#pragma unroll
        for (int c = 0; c < 8; c++) {
            int w = ((c & 1) << 7) | tid;
            int m = w >> 2, kc = (w & 3) << 3;
            const ushort_t* src;
            if ((c >> 1) == 0)      src = pAh + (size_t)(bm + m) * KPD + k0 + kc;
            else if ((c >> 1) == 1) src = pAl + (size_t)(bm + m) * KPD + k0 + kc;
            else if ((c >> 1) == 2) src = pBh + (size_t)(bn + m) * KPD + k0 + kc;
            else                    src = pBl + (size_t)(bn + m) * KPD + k0 + kc;
            cpa16(&smem[st][c >> 1][m * SLD + kc], src);
        }
        CP_COMMIT();
    };

    issue_tile(0, 0);
    for (int kt = 0; kt < 10; kt++) {
        CP_WAIT0();
        __syncthreads();
        if (kt + 1 < 10) issue_tile(kt + 1, (kt + 1) & 1);
        mma_tile(smem[kt & 1][0], smem[kt & 1][1], smem[kt & 1][2], smem[kt & 1][3],
                 warp_m, warp_n, lane, acc);
    }

    int quad = lane >> 2, tq = lane & 3;
#pragma unroll
    for (int mf = 0; mf < 2; mf++)
#pragma unroll
        for (int nf = 0; nf < 4; nf++) {
            int r0 = bm + warp_m + mf * 16 + quad;
            int c0 = bn + warp_n + nf * 8 + 2 * tq;
#pragma unroll
            for (int v = 0; v < 4; v++)
                Eb[(size_t)(r0 + (v >> 1) * 8) * Nn + c0 + (v & 1)] = acc[mf][nf][v];
        }
}

// ---------------------------------------------------------------------------
// conversion kernels (padded-layout outputs; pad regions never written = zero)
// ---------------------------------------------------------------------------
__global__ void cvt_chs_kernel(const float* __restrict__ src,
                               ushort_t* __restrict__ hi, ushort_t* __restrict__ lo) {
    int i = blockIdx.x * blockDim.x + threadIdx.x;
    if (i >= Bb * Nn * FIN) return;
    int r = i / FIN, c = i - r * FIN;
    float v = src[i];
    size_t o = (size_t)r * KPF + c;
    ushort_t h = f2bf(v);
    hi[o] = h;
    lo[o] = f2bf(v - bfbits2f(h));
}

__global__ void cvt_we_kernel(const float* __restrict__ src,
                              ushort_t* __restrict__ hi, ushort_t* __restrict__ lo) {
    int i = blockIdx.x * blockDim.x + threadIdx.x;
    if (i >= Dd * FIN) return;
    int r = i / FIN, c = i - r * FIN;
    float v = src[i];
    size_t o = (size_t)r * KPF + c;
    ushort_t h = f2bf(v);
    hi[o] = h;
    lo[o] = f2bf(v - bfbits2f(h));
}

__global__ void cvt_ww_kernel(const float* __restrict__ src,
                              ushort_t* __restrict__ hi, ushort_t* __restrict__ lo) {
    int i = blockIdx.x * blockDim.x + threadIdx.x;
    if (i >= LL * Dd * Dd) return;
    int l = i / (Dd * Dd), rem = i - l * Dd * Dd;
    int r = rem / Dd, c = rem - r * Dd;
    float v = src[i];
    size_t o = (size_t)l * NPD * KPD + (size_t)r * KPD + c;
    ushort_t h = f2bf(v);
    hi[o] = h;
    lo[o] = f2bf(v - bfbits2f(h));
}

__global__ void cvt_at_kernel(const float* __restrict__ src,
                              ushort_t* __restrict__ hi, ushort_t* __restrict__ lo) {
    int i = blockIdx.x * blockDim.x + threadIdx.x;
    if (i >= LL * Dd * Dd) return;
    int l = i / (Dd * Dd), rem = i - l * Dd * Dd;
    int r = rem / Dd, c = rem - r * Dd;
    float v = src[i];
    size_t o = (size_t)l * NPD * KPD + (size_t)c * KPD + r;  // transpose
    ushort_t h = f2bf(v);
    hi[o] = h;
    lo[o] = f2bf(v - bfbits2f(h));
}

// ---------------------------------------------------------------------------
__global__ void adj2_kernel(const float* __restrict__ a1,
                            const float* __restrict__ c2,
                            const float* __restrict__ mu,
                            const float* __restrict__ dv,
                            float* __restrict__ adj2, size_t total) {
    size_t i = (size_t)blockIdx.x * blockDim.x + threadIdx.x;
    if (i >= total) return;
    float d = c2[i] - mu[0];
    adj2[i] = expf(-d * d / dv[0]) + a1[i];
}

// ---------------------------------------------------------------------------
// Dual softmax over rows (axis=1): both adjacency branches, e read once.
// Each (tx,ty) thread exclusively owns 32 j-rows of column k -> registers.
// Writes att planes [b][br][j][k] (bf16 hi/lo).
// ---------------------------------------------------------------------------
__global__ __launch_bounds__(256)
void softmax2_kernel(const float* __restrict__ adj1,
                     const float* __restrict__ adj2,
                     const float* __restrict__ e,
                     ushort_t* __restrict__ atthi,
                     ushort_t* __restrict__ attlo) {
    __shared__ float red[16][16];
    int b = blockIdx.y;
    int tx = threadIdx.x, ty = threadIdx.y;
    int k = blockIdx.x * 16 + tx;
    const size_t base = (size_t)b * Nn * Nn;

    float ev[32];
#pragma unroll
    for (int t = 0; t < 32; t++)
        ev[t] = e[base + (size_t)(ty + 16 * t) * Nn + k];

    for (int br = 0; br < 2; br++) {
        const float* adj = br ? adj2 : adj1;
        size_t obase = ((size_t)b * 2 + br) * Nn * Nn;
        float av[32];
        float m = -3.4e38f;
#pragma unroll
        for (int t = 0; t < 32; t++) {
            av[t] = adj[base + (size_t)(ty + 16 * t) * Nn + k];
            float v = (av[t] > 0.f) ? ev[t] : NEGV;
            m = fmaxf(m, v);
        }
        red[ty][tx] = m;
        __syncthreads();
        if (ty == 0) {
            float mm = red[0][tx];
#pragma unroll
            for (int t = 1; t < 16; t++) mm = fmaxf(mm, red[t][tx]);
            red[0][tx] = mm;
        }
        __syncthreads();
        m = red[0][tx];
        __syncthreads();

        float s = 0.f;
        float xv[32];
#pragma unroll
        for (int t = 0; t < 32; t++) {
            float v = (av[t] > 0.f) ? ev[t] : NEGV;
            xv[t] = expf(v - m);
            s += xv[t];
        }
        red[ty][tx] = s;
        __syncthreads();
        if (ty == 0) {
            float ss = 0.f;
#pragma unroll
            for (int t = 0; t < 16; t++) ss += red[t][tx];
            red[0][tx] = ss;
        }
        __syncthreads();
        float inv = 1.f / red[0][tx];
        __syncthreads();

#pragma unroll
        for (int t = 0; t < 32; t++) {
            float v = xv[t] * inv * av[t];
            size_t idx = obase + (size_t)(ty + 16 * t) * Nn + k;
            ushort_t h = f2bf(v);
            atthi[idx] = h;
            attlo[idx] = f2bf(v - bfbits2f(h));
        }
    }
}

// ---------------------------------------------------------------------------
// Gated combine; hp layout [b][br][n][Dd]. Writes x f32 + x planes (KPD).
// ---------------------------------------------------------------------------
__global__ __launch_bounds__(256)
void gate_kernel(float* __restrict__ x,
                 ushort_t* __restrict__ xhi, ushort_t* __restrict__ xlo,
                 const float* __restrict__ hp,
                 const float* __restrict__ gwk,
                 const float* __restrict__ gbk) {
    int warp = (blockIdx.x * blockDim.x + threadIdx.x) >> 5;
    int lane = threadIdx.x & 31;
    if (warp >= Bb * Nn) return;
    size_t bb = warp >> 9, n = warp & 511;
    size_t roff = (size_t)warp * Dd;
    size_t hbase = ((bb * 2) * Nn + n) * Dd;
    float* xr = x + roff;
    const float* h1 = hp + hbase;
    const float* h2 = hp + hbase + (size_t)Nn * Dd;
    float sx = 0.f, s1 = 0.f, s2 = 0.f;
    for (int d = lane; d < Dd; d += 32) {
        float xv = xr[d];
        sx += xv * gwk[d];
        s1 += h1[d] * gwk[Dd + d];
        s2 += h2[d] * gwk[Dd + d];
    }
#pragma unroll
    for (int o = 16; o > 0; o >>= 1) {
        sx += __shfl_xor_sync(0xffffffffu, sx, o);
        s1 += __shfl_xor_sync(0xffffffffu, s1, o);
        s2 += __shfl_xor_sync(0xffffffffu, s2, o);
    }
    float gbv = gbk[0];
    float c1 = 1.f / (1.f + expf(-(sx + s1 + gbv)));
    float c2 = 1.f / (1.f + expf(-(sx + s2 + gbv)));
    size_t poff = (size_t)warp * KPD;
    for (int d = lane; d < Dd; d += 32) {
        float xv = xr[d], a = h1[d], bv = h2[d];
        float nv = (c2 * xv + (1.f - c2) * bv) - (c1 * xv + (1.f - c1) * a);
        xr[d] = nv;
        ushort_t h = f2bf(nv);
        xhi[poff + d] = h;
        xlo[poff + d] = f2bf(nv - bfbits2f(h));
    }
}

// ---------------------------------------------------------------------------
__global__ void readout_kernel(const float* __restrict__ x,
                               const float* __restrict__ valid,
                               float* __restrict__ g) {
    int b = blockIdx.x, d = threadIdx.x;
    if (d >= Dd) return;
    const float* xb = x + (size_t)b * Nn * Dd;
    const float* vb = valid + (size_t)b * Nn;
    float s = 0.f;
    for (int n = 0; n < Nn; n++) s += xb[(size_t)n * Dd + d] * vb[n];
    g[(size_t)b * Dd + d] = s;
}

__global__ __launch_bounds__(128)
void mlp_kernel(const float* __restrict__ g,
                const float* __restrict__ w0, const float* __restrict__ b0,
                const float* __restrict__ w1, const float* __restrict__ b1,
                const float* __restrict__ w2, const float* __restrict__ b2,
                const float* __restrict__ w3, const float* __restrict__ b3,
                float* __restrict__ out) {
    int b = blockIdx.x, t = threadIdx.x;
    __shared__ float gbuf[Dd];
    __shared__ float ha[DF];
    __shared__ float hb[DF];
    __shared__ float red[DF];
    for (int i = t; i < Dd; i += DF) gbuf[i] = g[(size_t)b * Dd + i];
    __syncthreads();
    float acc = b0[t];
    for (int k = 0; k < Dd; k++) acc += gbuf[k] * w0[(size_t)k * DF + t];
    ha[t] = fmaxf(acc, 0.f);
    __syncthreads();
    acc = b1[t];
    for (int k = 0; k < DF; k++) acc += ha[k] * w1[(size_t)k * DF + t];
    hb[t] = fmaxf(acc, 0.f);
    __syncthreads();
    acc = b2[t];
    for (int k = 0; k < DF; k++) acc += hb[k] * w2[(size_t)k * DF + t];
    ha[t] = fmaxf(acc, 0.f);
    __syncthreads();
    red[t] = ha[t] * w3[t];
    __syncthreads();
    for (int s = 64; s > 0; s >>= 1) {
        if (t < s) red[t] += red[t + s];
        __syncthreads();
    }
    if (t == 0) out[b] = 1.f / (1.f + expf(-(red[0] + b3[0])));
}

// ---------------------------------------------------------------------------
extern "C" void kernel_launch(void* const* d_in, const int* in_sizes, int n_in,
                              void* d_out, int out_size) {
    const float* c_hs  = (const float*)d_in[0];
    const float* adj1  = (const float*)d_in[1];
    const float* c2    = (const float*)d_in[2];
    const float* valid = (const float*)d_in[3];
    const float* We    = (const float*)d_in[4];
    const float* Ww    = (const float*)d_in[5];
    const float* Wb    = (const float*)d_in[6];
    const float* Amat  = (const float*)d_in[7];
    const float* gw    = (const float*)d_in[8];
    const float* gb    = (const float*)d_in[9];
    const float* mu    = (const float*)d_in[10];
    const float* dv    = (const float*)d_in[11];
    const float* w0 = (const float*)d_in[12]; const float* b0 = (const float*)d_in[13];
    const float* w1 = (const float*)d_in[14]; const float* b1 = (const float*)d_in[15];
    const float* w2 = (const float*)d_in[16]; const float* b2 = (const float*)d_in[17];
    const float* w3 = (const float*)d_in[18]; const float* b3 = (const float*)d_in[19];
    float* out = (float*)d_out;

    float* fbase = nullptr;
    cudaGetSymbolAddress((void**)&fbase, g_f32);
    float* x    = fbase;                          // [Bb*Nn][Dd]
    float* hp   = fbase + (size_t)BNDc;           // [Bb][2][Nn][Dd]
    float* e    = hp + 2ull * BNDc;               // [Bb][Nn][Nn]
    float* adj2 = e + (size_t)BNNc;
    float* g    = adj2 + (size_t)BNNc;

    ushort_t* u = nullptr;
    cudaGetSymbolAddress((void**)&u, g_bf);
    ushort_t* xhi  = u;                 ushort_t* xlo  = xhi + XPLs;
    ushort_t* hhi  = xlo + XPLs;        ushort_t* hlo  = hhi + XPLs;
    ushort_t* hAhi = hlo + XPLs;        ushort_t* hAlo = hAhi + XPLs;
    ushort_t* hThi = hAlo + XPLs;       ushort_t* hTlo = hThi + HTs;
    ushort_t* atthi = hTlo + HTs;       ushort_t* attlo = atthi + ATTs;
    ushort_t* chshi = attlo + ATTs;     ushort_t* chslo = chshi + CHSs;
    ushort_t* Wehi  = chslo + CHSs;     ushort_t* Welo  = Wehi + WEs;
    ushort_t* Wwhi  = Welo + WEs;       ushort_t* Wwlo  = Wwhi + WWs;
    ushort_t* AThi  = Wwlo + WWs;       ushort_t* ATlo  = AThi + WWs;

    int M = Bb * Nn;

    cvt_chs_kernel<<<(Bb * Nn * FIN + 255) / 256, 256>>>(c_hs, chshi, chslo);
    cvt_we_kernel<<<(Dd * FIN + 255) / 256, 256>>>(We, Wehi, Welo);
    cvt_ww_kernel<<<(LL * Dd * Dd + 255) / 256, 256>>>(Ww, Wwhi, Wwlo);
    cvt_at_kernel<<<(LL * Dd * Dd + 255) / 256, 256>>>(Amat, AThi, ATlo);
    adj2_kernel<<<(unsigned)(((size_t)BNNc + 255) / 256), 256>>>(adj1, c2, mu, dv, adj2, BNNc);

    // embed: x = chs @ We^T  (f32 + planes)
    gemm_ca<1 | 2, 0><<<dim3(3, M / 64, 1), 128>>>(
        chshi, chslo, Wehi, Welo, nullptr,
        x, xhi, xlo, nullptr, nullptr,
        Dd, KPF, KPF, KPF, KPD, 0, 0, 0);

    for (int k = 0; k < LL; k++) {
        const float* Wbk = Wb + (size_t)k * Dd;
        const float* gwk = gw + (size_t)k * 2 * Dd;
        const float* gbk = gb + k;
        size_t woff = (size_t)k * NPD * KPD;

        // h = x @ Ww^T + Wb  (planes + hT planes)
        gemm_ca<2 | 4 | 16, 0><<<dim3(3, M / 64, 1), 128>>>(
            xhi, xlo, Wwhi + woff, Wwlo + woff, Wbk,
            nullptr, hhi, hlo, hThi, hTlo,
            Dd, KPD, KPD, KPD, KPD, 0, 0, 0);

        // hA = h @ A  (planes)
        gemm_ca<2, 0><<<dim3(3, M / 64, 1), 128>>>(
            hhi, hlo, AThi + woff, ATlo + woff, nullptr,
            nullptr, hAhi, hAlo, nullptr, nullptr,
            Dd, KPD, KPD, KPD, KPD, 0, 0, 0);

        // e = hA h^T + h hA^T
        esym_ca<<<dim3(Nn / 64, Nn / 64, Bb), 128>>>(hhi, hlo, hAhi, hAlo, e);

        // both softmaxes in one pass
        softmax2_kernel<<<dim3(Nn / 16, Bb), dim3(16, 16)>>>(
            adj1, adj2, e, atthi, attlo);

        // both att@h branches in one batched launch (z = b*2+br)
        gemm_ca<1 | 8, 1><<<dim3(3, Nn / 64, 2 * Bb), 128>>>(
            atthi, attlo, hThi, hTlo, nullptr,
            hp, nullptr, nullptr, nullptr, nullptr,
            Dd, Nn, Nn, Nn, KPD,
            (size_t)Nn * Nn, (size_t)NPD * Nn, (size_t)Nn * Dd);

        gate_kernel<<<(Bb * Nn) / 8, 256>>>(x, xhi, xlo, hp, gwk, gbk);
    }

    readout_kernel<<<Bb, 160>>>(x, valid, g);
    mlp_kernel<<<Bb, DF>>>(g, w0, b0, w1, b1, w2, b2, w3, b3, out);
}